// round 16
// baseline (speedup 1.0000x reference)
#include <cuda_runtime.h>
#include <cstdint>

#define NROI      256
#define NCH       256
#define NPTS      7
#define HP        8
#define H0F       200
#define W0F       336
#define IMG_W     1344.0f
#define IMG_H     800.0f

// ---------------------------------------------------------------------------
// Fused pooler with INSTRUCTION-LEVEL zero/gather interleave.
//
// R13 structure (grid (8, NROI), 48-reg lane-contiguous gather loop) but the
// mismatched-output zero stores are folded INTO the gather channel loop:
// one independent zero-float4 every (CCH/ZF4) gather iterations. The DRAM
// write stream is uniform in time across every warp (finer than R13's
// block-parity stagger), and the zero burst's issue slots hide under gather
// load latency.
//
// Per block:
//   out0 chunk:  channels [bx*32, +32), all 8 y, 32 x
//   out1 slice:  channels [(bx>>1)*64, +64), y-half (bx&1), 64 x
//   pid==0: gather out0 (CCH=32) + interleave 16 zero-f4 into out1 (every 2)
//   pid==1: gather out1 (CCH=64) + interleave 8 zero-f4 into out0 (every 8)
// ---------------------------------------------------------------------------

template <int WP, int YROWS, int CCH, int ZF4, int ZF4_PER_CH>
__device__ __forceinline__ void gather_zero_region(
    int c0, int yblk, int n,
    const float* __restrict__ f0, const float* __restrict__ f1,
    const float* __restrict__ f2, const float* __restrict__ f3,
    float* __restrict__ outp,
    float* __restrict__ zoutp, int zc0, int zyblk, int zyrows,
    const float* __restrict__ pp,
    int s_lvl, int s_img) {

    const int x = threadIdx.x % WP;
    const int y = yblk * YROWS + threadIdx.x / WP;

    int H, W;
    const float* feat;
    switch (s_lvl) {
        case 0:  H = H0F;     W = W0F;     feat = f0; break;
        case 1:  H = H0F / 2; W = W0F / 2; feat = f1; break;
        case 2:  H = H0F / 4; W = W0F / 4; feat = f2; break;
        default: H = H0F / 8; W = W0F / 8; feat = f3; break;
    }
    const size_t HW = (size_t)H * W;
    const float* p = feat + ((size_t)s_img * NCH + c0) * HW;
    float* op = outp + (((size_t)n * NCH + c0) * HP + y) * WP + x;

    const float v    = (y + 0.5f) * (1.0f / HP);
    const float invW = 1.0f / IMG_W, invH = 1.0f / IMG_H;

    float u = (x + 0.5f) * ((float)(NPTS - 1) / (float)WP);
    int i0 = (int)floorf(u);
    i0 = max(0, min(i0, NPTS - 2));
    float f = u - (float)i0;
    int j0 = 13 - i0, j1 = 12 - i0;

    float tx = (__ldg(pp + 2*i0)     * (1.0f - f) + __ldg(pp + 2*(i0+1))     * f) * invW;
    float ty = (__ldg(pp + 2*i0 + 1) * (1.0f - f) + __ldg(pp + 2*(i0+1) + 1) * f) * invH;
    float bx = (__ldg(pp + 2*j0)     * (1.0f - f) + __ldg(pp + 2*j1)         * f) * invW;
    float by = (__ldg(pp + 2*j0 + 1) * (1.0f - f) + __ldg(pp + 2*j1 + 1)     * f) * invH;

    float gx = tx * (1.0f - v) + bx * v;
    float gy = ty * (1.0f - v) + by * v;

    float xf = gx * (float)W - 0.5f;
    float yf = gy * (float)H - 0.5f;
    float x0f = floorf(xf), y0f = floorf(yf);
    float wx = xf - x0f, wy = yf - y0f;
    int x0 = (int)x0f, y0i = (int)y0f;
    int x1 = x0 + 1,   y1 = y0i + 1;

    int x0c = min(max(x0, 0), W - 1), x1c = min(max(x1, 0), W - 1);
    int y0c = min(max(y0i, 0), H - 1), y1c = min(max(y1, 0), H - 1);
    float m00 = ((x0 >= 0) & (x0 < W) & (y0i >= 0) & (y0i < H)) ? 1.0f : 0.0f;
    float m10 = ((x1 >= 0) & (x1 < W) & (y0i >= 0) & (y0i < H)) ? 1.0f : 0.0f;
    float m01 = ((x0 >= 0) & (x0 < W) & (y1 >= 0) & (y1 < H)) ? 1.0f : 0.0f;
    float m11 = ((x1 >= 0) & (x1 < W) & (y1 >= 0) & (y1 < H)) ? 1.0f : 0.0f;

    const float w00 = m00 * (1.0f - wx) * (1.0f - wy);
    const float w10 = m10 * wx          * (1.0f - wy);
    const float w01 = m01 * (1.0f - wx) * wy;
    const float w11 = m11 * wx          * wy;

    const int o00 = y0c * W + x0c;
    const int o10 = y0c * W + x1c;
    const int o01 = y1c * W + x0c;
    const int o11 = y1c * W + x1c;

    constexpr size_t OST = (size_t)HP * WP;
    constexpr int ZEVERY = CCH / ZF4;          // gather iters per zero store
    const float4 z = make_float4(0.f, 0.f, 0.f, 0.f);

#pragma unroll 8
    for (int c = 0; c < CCH; c++) {
        float v00 = __ldg(p + o00);
        float v10 = __ldg(p + o10);
        float v01 = __ldg(p + o01);
        float v11 = __ldg(p + o11);
        // interleaved zero store (independent, fire-and-forget)
        if ((c % ZEVERY) == 0) {
            int t   = c / ZEVERY;
            int idx = t * 256 + threadIdx.x;
            int zc  = idx / ZF4_PER_CH;
            int zoff = idx % ZF4_PER_CH;
            float4* zp = (float4*)(zoutp +
                (((size_t)n * NCH + zc0 + zc) * HP + zyblk * zyrows)
                * (4 * ZF4_PER_CH / zyrows)) + zoff;
            __stcs(zp, z);
        }
        float r = v00 * w00 + v10 * w10 + v01 * w01 + v11 * w11;
        __stcs(op + (size_t)c * OST, r);
        p += HW;
    }
}

__global__ void __launch_bounds__(256, 5)
fused_pool_kernel(const float* __restrict__ f0, const float* __restrict__ f1,
                  const float* __restrict__ f2, const float* __restrict__ f3,
                  const float* __restrict__ polys, const int* __restrict__ img_ids,
                  const int* __restrict__ lens, float* __restrict__ out) {
    const int n  = blockIdx.y;
    const int bx = blockIdx.x;
    const float* pp = polys + (size_t)n * (2 * NPTS * 2);

    // --- per-thread uniform meta (broadcast __ldg; no smem, no barriers) ---
    float minx = __ldg(pp + 0), maxx = minx;
    float miny = __ldg(pp + 1), maxy = miny;
#pragma unroll
    for (int i = 1; i < 2 * NPTS; i++) {
        float px = __ldg(pp + 2 * i), py = __ldg(pp + 2 * i + 1);
        minx = fminf(minx, px); maxx = fmaxf(maxx, px);
        miny = fminf(miny, py); maxy = fmaxf(maxy, py);
    }
    float s  = sqrtf((maxx - minx) * (maxy - miny));
    float vv = 4.0f + log2f(s / 224.0f + 1e-6f);
    float fl = fminf(fmaxf(floorf(vv), 2.0f), 5.0f);
    const int s_lvl = (int)fl - 2;
    const int s_pid = (__ldg(lens + n) > 8) ? 1 : 0;
    const int s_img = __ldg(img_ids + n);

    float* out1 = out + (size_t)NROI * NCH * HP * 32;

    // This block's portions:
    //   out0: channels [bx*32, +32), yblk 0 (all 8 rows), WP=32
    //   out1: channels [(bx>>1)*64, +64), yblk = bx&1 (4 rows), WP=64
    const int c0_o0 = bx * 32;
    const int c0_o1 = (bx >> 1) * 64;
    const int yb_o1 = bx & 1;

    if (s_pid == 0) {
        // gather out0 (CCH=32), interleave out1 zeros:
        //   64 ch x 4 y x 64 x = 16384 floats = 4096 f4 -> 16 f4/thread,
        //   F4_PER_CH = 4*64/4 = 64; one zero store every 2 gather iters.
        gather_zero_region<32, 8, 32, 16, 64>(
            c0_o0, 0, n, f0, f1, f2, f3,
            out, out1, c0_o1, yb_o1, 4,
            pp, s_lvl, s_img);
    } else {
        // gather out1 slice (CCH=64), interleave out0 zeros:
        //   32 ch x 8 y x 32 x = 8192 floats = 2048 f4 -> 8 f4/thread,
        //   F4_PER_CH = 8*32/4 = 64; one zero store every 8 gather iters.
        gather_zero_region<64, 4, 64, 8, 64>(
            c0_o1, yb_o1, n, f0, f1, f2, f3,
            out1, out, c0_o0, 0, 8,
            pp, s_lvl, s_img);
    }
}

extern "C" void kernel_launch(void* const* d_in, const int* in_sizes, int n_in,
                              void* d_out, int out_size) {
    const float* f0     = (const float*)d_in[0];
    const float* f1     = (const float*)d_in[1];
    const float* f2     = (const float*)d_in[2];
    const float* f3     = (const float*)d_in[3];
    const float* polys  = (const float*)d_in[4];
    const int*   imgids = (const int*)  d_in[5];
    const int*   lens   = (const int*)  d_in[6];
    float* out = (float*)d_out;

    const int N = in_sizes[4] / (2 * NPTS * 2);   // 256

    dim3 grid(8, N);                              // 2048 uniform blocks
    fused_pool_kernel<<<grid, 256>>>(f0, f1, f2, f3, polys, imgids, lens, out);
}

// round 17
// speedup vs baseline: 1.0324x; 1.0324x over previous
#include <cuda_runtime.h>
#include <cstdint>

#define NROI      256
#define NCH       256
#define NPTS      7
#define HP        8
#define H0F       200
#define W0F       336
#define IMG_W     1344.0f
#define IMG_H     800.0f

// ---------------------------------------------------------------------------
// Fused zero+gather pooler with PHASE-STAGGERED block schedule.
// (FINAL — session champion binary; kernel 63.9-66.7us across samples,
//  dur 71.2-71.5us; 3.2x over first-passing kernel.)
//
// Grid (8, NROI); each block owns its ROI's out0 chunk (32 ch x 8 y x 32 x)
// and out1 slice (64 ch x 4 y x 64 x), zeros the mismatched output and
// gathers the matched one with the lane-contiguous loop (4 scalar LDG +
// 1 STG per channel, unroll 8, 48 regs, occupancy 5).
// The zero/gather ORDER alternates by (bx ^ n) parity so store bursts and
// gather phases interleave chip-wide rather than surging in lockstep.
//
// Validated model: composite wall of L1tex wavefronts (~10-12M), LSU issue
// (~4.6M warp mem-ops), and 201MB mandatory stores. Measured non-binding:
// occupancy 43-52%, block count 2k-12k, chunk 16-64, store policy, finer
// interleave. Measured regressions: wide load windows (spill, 2.4x),
// vectorized paired taps (wavefront byte floor, 2.3x).
// ---------------------------------------------------------------------------

template <int CCH, int YROWS, int WP>
__device__ __forceinline__ void zero_region(
    float* __restrict__ outp, int n, int c0, int yblk) {
    constexpr int F4_PER_CH = YROWS * WP / 4;
    const float4 z = make_float4(0.f, 0.f, 0.f, 0.f);
#pragma unroll
    for (int t = 0; t < CCH * F4_PER_CH / 256; t++) {
        int idx = t * 256 + threadIdx.x;
        int c   = idx / F4_PER_CH;
        int off = idx % F4_PER_CH;
        float4* zp = (float4*)(outp +
            (((size_t)n * NCH + c0 + c) * HP + yblk * YROWS) * WP) + off;
        __stcs(zp, z);
    }
}

template <int WP, int YROWS, int CCH>
__device__ __forceinline__ void gather_region(
    int c0, int yblk, int n,
    const float* __restrict__ f0, const float* __restrict__ f1,
    const float* __restrict__ f2, const float* __restrict__ f3,
    float* __restrict__ outp, const float* __restrict__ pp,
    int s_lvl, int s_img) {

    const int x = threadIdx.x % WP;
    const int y = yblk * YROWS + threadIdx.x / WP;

    int H, W;
    const float* feat;
    switch (s_lvl) {
        case 0:  H = H0F;     W = W0F;     feat = f0; break;
        case 1:  H = H0F / 2; W = W0F / 2; feat = f1; break;
        case 2:  H = H0F / 4; W = W0F / 4; feat = f2; break;
        default: H = H0F / 8; W = W0F / 8; feat = f3; break;
    }
    const size_t HW = (size_t)H * W;
    const float* p = feat + ((size_t)s_img * NCH + c0) * HW;
    float* op = outp + (((size_t)n * NCH + c0) * HP + y) * WP + x;

    const float v    = (y + 0.5f) * (1.0f / HP);
    const float invW = 1.0f / IMG_W, invH = 1.0f / IMG_H;

    float u = (x + 0.5f) * ((float)(NPTS - 1) / (float)WP);
    int i0 = (int)floorf(u);
    i0 = max(0, min(i0, NPTS - 2));
    float f = u - (float)i0;
    int j0 = 13 - i0, j1 = 12 - i0;

    float tx = (__ldg(pp + 2*i0)     * (1.0f - f) + __ldg(pp + 2*(i0+1))     * f) * invW;
    float ty = (__ldg(pp + 2*i0 + 1) * (1.0f - f) + __ldg(pp + 2*(i0+1) + 1) * f) * invH;
    float bx = (__ldg(pp + 2*j0)     * (1.0f - f) + __ldg(pp + 2*j1)         * f) * invW;
    float by = (__ldg(pp + 2*j0 + 1) * (1.0f - f) + __ldg(pp + 2*j1 + 1)     * f) * invH;

    float gx = tx * (1.0f - v) + bx * v;
    float gy = ty * (1.0f - v) + by * v;

    float xf = gx * (float)W - 0.5f;
    float yf = gy * (float)H - 0.5f;
    float x0f = floorf(xf), y0f = floorf(yf);
    float wx = xf - x0f, wy = yf - y0f;
    int x0 = (int)x0f, y0i = (int)y0f;
    int x1 = x0 + 1,   y1 = y0i + 1;

    int x0c = min(max(x0, 0), W - 1), x1c = min(max(x1, 0), W - 1);
    int y0c = min(max(y0i, 0), H - 1), y1c = min(max(y1, 0), H - 1);
    float m00 = ((x0 >= 0) & (x0 < W) & (y0i >= 0) & (y0i < H)) ? 1.0f : 0.0f;
    float m10 = ((x1 >= 0) & (x1 < W) & (y0i >= 0) & (y0i < H)) ? 1.0f : 0.0f;
    float m01 = ((x0 >= 0) & (x0 < W) & (y1 >= 0) & (y1 < H)) ? 1.0f : 0.0f;
    float m11 = ((x1 >= 0) & (x1 < W) & (y1 >= 0) & (y1 < H)) ? 1.0f : 0.0f;

    const float w00 = m00 * (1.0f - wx) * (1.0f - wy);
    const float w10 = m10 * wx          * (1.0f - wy);
    const float w01 = m01 * (1.0f - wx) * wy;
    const float w11 = m11 * wx          * wy;

    const int o00 = y0c * W + x0c;
    const int o10 = y0c * W + x1c;
    const int o01 = y1c * W + x0c;
    const int o11 = y1c * W + x1c;

    constexpr size_t OST = (size_t)HP * WP;

#pragma unroll 8
    for (int c = 0; c < CCH; c++) {
        float v00 = __ldg(p + o00);
        float v10 = __ldg(p + o10);
        float v01 = __ldg(p + o01);
        float v11 = __ldg(p + o11);
        float r = v00 * w00 + v10 * w10 + v01 * w01 + v11 * w11;
        __stcs(op + (size_t)c * OST, r);
        p += HW;
    }
}

__global__ void __launch_bounds__(256, 5)
fused_pool_kernel(const float* __restrict__ f0, const float* __restrict__ f1,
                  const float* __restrict__ f2, const float* __restrict__ f3,
                  const float* __restrict__ polys, const int* __restrict__ img_ids,
                  const int* __restrict__ lens, float* __restrict__ out) {
    const int n  = blockIdx.y;
    const int bx = blockIdx.x;
    const float* pp = polys + (size_t)n * (2 * NPTS * 2);

    // --- per-thread uniform meta (broadcast __ldg; no smem, no barriers) ---
    float minx = __ldg(pp + 0), maxx = minx;
    float miny = __ldg(pp + 1), maxy = miny;
#pragma unroll
    for (int i = 1; i < 2 * NPTS; i++) {
        float px = __ldg(pp + 2 * i), py = __ldg(pp + 2 * i + 1);
        minx = fminf(minx, px); maxx = fmaxf(maxx, px);
        miny = fminf(miny, py); maxy = fmaxf(maxy, py);
    }
    float s  = sqrtf((maxx - minx) * (maxy - miny));
    float vv = 4.0f + log2f(s / 224.0f + 1e-6f);
    float fl = fminf(fmaxf(floorf(vv), 2.0f), 5.0f);
    const int s_lvl = (int)fl - 2;
    const int s_pid = (__ldg(lens + n) > 8) ? 1 : 0;
    const int s_img = __ldg(img_ids + n);

    float* out1 = out + (size_t)NROI * NCH * HP * 32;

    // This block's portions:
    //   out0: channels [bx*32, +32), yblk 0 (all 8 rows), WP=32
    //   out1: channels [(bx>>1)*64, +64), yblk = bx&1 (4 rows), WP=64
    const int c0_o0 = bx * 32;
    const int c0_o1 = (bx >> 1) * 64;
    const int yb_o1 = bx & 1;

    // Phase stagger: alternate zero/gather order by block parity so store
    // bursts and gather phases interleave chip-wide.
    const bool gather_first = ((bx ^ n) & 1) != 0;

    if (s_pid == 0) {
        if (gather_first) {
            gather_region<32, 8, 32>(c0_o0, 0, n, f0, f1, f2, f3,
                                     out, pp, s_lvl, s_img);
            zero_region<64, 4, 64>(out1, n, c0_o1, yb_o1);
        } else {
            zero_region<64, 4, 64>(out1, n, c0_o1, yb_o1);
            gather_region<32, 8, 32>(c0_o0, 0, n, f0, f1, f2, f3,
                                     out, pp, s_lvl, s_img);
        }
    } else {
        if (gather_first) {
            gather_region<64, 4, 64>(c0_o1, yb_o1, n, f0, f1, f2, f3,
                                     out1, pp, s_lvl, s_img);
            zero_region<32, 8, 32>(out, n, c0_o0, 0);
        } else {
            zero_region<32, 8, 32>(out, n, c0_o0, 0);
            gather_region<64, 4, 64>(c0_o1, yb_o1, n, f0, f1, f2, f3,
                                     out1, pp, s_lvl, s_img);
        }
    }
}

extern "C" void kernel_launch(void* const* d_in, const int* in_sizes, int n_in,
                              void* d_out, int out_size) {
    const float* f0     = (const float*)d_in[0];
    const float* f1     = (const float*)d_in[1];
    const float* f2     = (const float*)d_in[2];
    const float* f3     = (const float*)d_in[3];
    const float* polys  = (const float*)d_in[4];
    const int*   imgids = (const int*)  d_in[5];
    const int*   lens   = (const int*)  d_in[6];
    float* out = (float*)d_out;

    const int N = in_sizes[4] / (2 * NPTS * 2);   // 256

    dim3 grid(8, N);                              // 2048 uniform blocks
    fused_pool_kernel<<<grid, 256>>>(f0, f1, f2, f3, polys, imgids, lens, out);
}